// round 1
// baseline (speedup 1.0000x reference)
#include <cuda_runtime.h>

#define Bx 4
#define Nx 4096
#define Cx 1024
#define Dx 32
#define Hx 32
#define NC3 3072
#define EPSV 1e-15f

// Scratch (device globals — no allocation allowed)
__device__ float g_qkv[(size_t)Bx * Nx * NC3];        // 192 MB
__device__ float g_vkpart[1024 * 1056];               // 4.3 MB  (128 heads x 8 slices x 33x32)
__device__ float g_vk[128 * 1056];                    // 0.5 MB
__device__ float g_att[(size_t)Bx * Nx * Cx];         // 64 MB

// ---------------------------------------------------------------------------
// Generic SGEMM: C[m,n] = sum_k A[m,k] * W[n,k]   (both row-major, K-contiguous)
// MODE 0: relu on cols < relu_upto (qkv epilogue). MODE 1: add bias[n].
// BM=BN=128, BK=16, 256 threads, 8x8 per thread.
// ---------------------------------------------------------------------------
template <int MODE>
__global__ __launch_bounds__(256) void sgemm_kernel(
    const float* __restrict__ A, const float* __restrict__ W,
    float* __restrict__ Cout, const float* __restrict__ bias,
    int M, int Nn, int K, int relu_upto)
{
    __shared__ float As[16][128];
    __shared__ float Ws[16][128];

    const int tid = threadIdx.x;
    const int n0 = blockIdx.x * 128;
    const int m0 = blockIdx.y * 128;
    const int tx = tid & 15;
    const int ty = tid >> 4;

    float acc[8][8];
#pragma unroll
    for (int i = 0; i < 8; i++)
#pragma unroll
        for (int j = 0; j < 8; j++) acc[i][j] = 0.0f;

    const float* Aptr = A + (size_t)m0 * K;
    const float* Wptr = W + (size_t)n0 * K;

    for (int kt = 0; kt < K; kt += 16) {
#pragma unroll
        for (int i = 0; i < 2; i++) {
            int idx = tid * 2 + i;          // 0..511
            int row = idx >> 2;
            int c4  = (idx & 3) * 4;
            float4 a = *(const float4*)(Aptr + (size_t)row * K + kt + c4);
            As[c4 + 0][row] = a.x; As[c4 + 1][row] = a.y;
            As[c4 + 2][row] = a.z; As[c4 + 3][row] = a.w;
            float4 b = *(const float4*)(Wptr + (size_t)row * K + kt + c4);
            Ws[c4 + 0][row] = b.x; Ws[c4 + 1][row] = b.y;
            Ws[c4 + 2][row] = b.z; Ws[c4 + 3][row] = b.w;
        }
        __syncthreads();

#pragma unroll
        for (int kk = 0; kk < 16; kk++) {
            float ar[8], br[8];
            *(float4*)(ar)     = *(const float4*)&As[kk][ty * 8];
            *(float4*)(ar + 4) = *(const float4*)&As[kk][ty * 8 + 4];
            *(float4*)(br)     = *(const float4*)&Ws[kk][tx * 8];
            *(float4*)(br + 4) = *(const float4*)&Ws[kk][tx * 8 + 4];
#pragma unroll
            for (int i = 0; i < 8; i++)
#pragma unroll
                for (int j = 0; j < 8; j++) acc[i][j] += ar[i] * br[j];
        }
        __syncthreads();
    }

#pragma unroll
    for (int i = 0; i < 8; i++) {
        int m = m0 + ty * 8 + i;
#pragma unroll
        for (int j = 0; j < 8; j++) {
            int n = n0 + tx * 8 + j;
            float v = acc[i][j];
            if (MODE == 0) {
                if (n < relu_upto) v = fmaxf(v, 0.0f);
            } else {
                v += bias[n];
            }
            Cout[(size_t)m * Nn + n] = v;
        }
    }
}

// ---------------------------------------------------------------------------
// vk partial reduction. grid = 1024 blocks: block = (head 0..127, slice 0..7).
// Each block reduces 512 n-rows into a 33x32 partial outer-product sum.
// vk[d][e] = sum_n v_ext[d,n] * k[n,e],   v_ext[32,:]=1, k already relu'd.
// ---------------------------------------------------------------------------
__global__ __launch_bounds__(256) void vk_partial_kernel(
    const float* __restrict__ qkv, float* __restrict__ part)
{
    const int blk   = blockIdx.x;
    const int slice = blk & 7;
    const int head  = blk >> 3;             // 0..127
    const int b  = head >> 5;
    const int hh = head & 31;
    const int tid = threadIdx.x;

    __shared__ float ks[8][32];
    __shared__ float vs[8][32];

    float acc[5] = {0.f, 0.f, 0.f, 0.f, 0.f};

    const float* base = qkv + (size_t)b * Nx * NC3 + (size_t)(slice * 512) * NC3
                        + hh * 32;
    const int r = tid >> 5;
    const int e = tid & 31;

    for (int n0 = 0; n0 < 512; n0 += 8) {
        const float* p = base + (size_t)(n0 + r) * NC3 + e;
        float kreg = p[1024];   // k block (relu applied in GEMM epilogue)
        float vreg = p[2048];   // v block
        __syncthreads();        // previous chunk's compute done
        ks[r][e] = kreg;
        vs[r][e] = vreg;
        __syncthreads();
#pragma unroll
        for (int rr = 0; rr < 8; rr++) {
#pragma unroll
            for (int i = 0; i < 5; i++) {
                int idx = tid + 256 * i;
                if (idx < 1056) {
                    int d  = idx >> 5;
                    int ee = idx & 31;
                    float vval = (d == 32) ? 1.0f : vs[rr][d];
                    acc[i] += vval * ks[rr][ee];
                }
            }
        }
    }
#pragma unroll
    for (int i = 0; i < 5; i++) {
        int idx = tid + 256 * i;
        if (idx < 1056) part[(size_t)blk * 1056 + idx] = acc[i];
    }
}

__global__ void vk_reduce_kernel(const float* __restrict__ part,
                                 float* __restrict__ vk)
{
    int idx = blockIdx.x * 256 + threadIdx.x;
    if (idx >= 128 * 1056) return;
    int head = idx / 1056;
    int j    = idx % 1056;
    float s = 0.f;
#pragma unroll
    for (int sl = 0; sl < 8; sl++)
        s += part[(size_t)(head * 8 + sl) * 1056 + j];
    vk[idx] = s;
}

// ---------------------------------------------------------------------------
// att kernel: out[b,n,hh*32+d] = (vk[d,:] . q_n) / (vk[32,:] . q_n + eps)
// grid = 4096 blocks (head 0..127, nchunk 0..31), 128 threads (1 thread / n).
// ---------------------------------------------------------------------------
__global__ __launch_bounds__(128) void att_kernel(
    const float* __restrict__ qkv, const float* __restrict__ vk,
    float* __restrict__ att)
{
    const int blk  = blockIdx.x;
    const int nch  = blk & 31;
    const int head = blk >> 5;
    const int b  = head >> 5;
    const int hh = head & 31;
    const int tid = threadIdx.x;

    __shared__ float vks[1056];
    __shared__ float qs[128][33];

    for (int i = tid; i < 1056; i += 128)
        vks[i] = vk[(size_t)head * 1056 + i];

    const float* qbase = qkv + (size_t)b * Nx * NC3 + (size_t)(nch * 128) * NC3
                         + hh * 32;
#pragma unroll
    for (int i = 0; i < 32; i++) {
        int idx = i * 128 + tid;
        int row = idx >> 5;
        int e   = idx & 31;
        qs[row][e] = qbase[(size_t)row * NC3 + e];
    }
    __syncthreads();

    float qr[32];
#pragma unroll
    for (int e = 0; e < 32; e++) qr[e] = qs[tid][e];

    float den = 0.f;
#pragma unroll
    for (int e = 0; e < 32; e++) den += vks[1024 + e] * qr[e];
    float inv = 1.0f / (den + EPSV);

    float outv[32];
#pragma unroll
    for (int d = 0; d < 32; d++) {
        float s = 0.f;
#pragma unroll
        for (int e = 0; e < 32; e++) s += vks[d * 32 + e] * qr[e];
        outv[d] = s * inv;
    }
    __syncthreads();
#pragma unroll
    for (int d = 0; d < 32; d++) qs[tid][d] = outv[d];
    __syncthreads();

    float* obase = att + (size_t)b * Nx * Cx + (size_t)(nch * 128) * Cx + hh * 32;
#pragma unroll
    for (int i = 0; i < 32; i++) {
        int idx = i * 128 + tid;
        int row = idx >> 5;
        int d   = idx & 31;
        obase[(size_t)row * Cx + d] = qs[row][d];
    }
}

// ---------------------------------------------------------------------------
extern "C" void kernel_launch(void* const* d_in, const int* in_sizes, int n_in,
                              void* d_out, int out_size)
{
    const float* x     = (const float*)d_in[0];
    const float* Wqkv  = (const float*)d_in[1];
    const float* Wproj = (const float*)d_in[2];
    const float* bproj = (const float*)d_in[3];
    float* out = (float*)d_out;

    float *qkv, *part, *vk, *att;
    cudaGetSymbolAddress((void**)&qkv,  g_qkv);
    cudaGetSymbolAddress((void**)&part, g_vkpart);
    cudaGetSymbolAddress((void**)&vk,   g_vk);
    cudaGetSymbolAddress((void**)&att,  g_att);

    const int M = Bx * Nx;   // 16384

    // 1) qkv = x @ Wqkv^T, relu on q,k channels (< 2048)
    {
        dim3 grid(NC3 / 128, M / 128);
        sgemm_kernel<0><<<grid, 256>>>(x, Wqkv, qkv, nullptr, M, NC3, Cx, 2 * Cx);
    }
    // 2) vk partials (split-8 over N) + reduce
    vk_partial_kernel<<<1024, 256>>>(qkv, part);
    vk_reduce_kernel<<<(128 * 1056 + 255) / 256, 256>>>(part, vk);
    // 3) attention normalize -> att (B,N,C)
    att_kernel<<<4096, 128>>>(qkv, vk, att);
    // 4) out = att @ Wproj^T + b
    {
        dim3 grid(Cx / 128, M / 128);
        sgemm_kernel<1><<<grid, 256>>>(att, Wproj, out, bproj, M, Cx, Cx, 0);
    }
}

// round 3
// speedup vs baseline: 2.0458x; 2.0458x over previous
#include <cuda_runtime.h>
#include <cstdint>

#define Bx 4
#define Nx 4096
#define Cx 1024
#define NC3 3072
#define EPSV 1e-15f

// Scratch (device globals — no allocation allowed)
__device__ float g_qkv[(size_t)Bx * Nx * NC3];        // 192 MB
__device__ float g_vkpart[1024 * 1056];               // 4.3 MB
__device__ float g_vk[128 * 1056];                    // 0.5 MB
__device__ float g_att[(size_t)Bx * Nx * Cx];         // 64 MB

__device__ __forceinline__ float tf32r(float a) {
    uint32_t b;
    asm("cvt.rna.tf32.f32 %0, %1;" : "=r"(b) : "f"(a));
    return __uint_as_float(b);
}

__device__ __forceinline__ void mma_tf32(float d[4], const float a[4],
                                         float b0, float b1) {
    asm("mma.sync.aligned.m16n8k8.row.col.f32.tf32.tf32.f32 "
        "{%0,%1,%2,%3}, {%4,%5,%6,%7}, {%8,%9}, {%0,%1,%2,%3};"
        : "+f"(d[0]), "+f"(d[1]), "+f"(d[2]), "+f"(d[3])
        : "r"(__float_as_uint(a[0])), "r"(__float_as_uint(a[1])),
          "r"(__float_as_uint(a[2])), "r"(__float_as_uint(a[3])),
          "r"(__float_as_uint(b0)), "r"(__float_as_uint(b1)));
}

// ---------------------------------------------------------------------------
// Tensor-core GEMM via legacy mma.sync (tf32): C[m,n] = sum_k A[m,k]*W[n,k]
// NCHAIN=2: W split into hi+lo tf32 (chained) -> ~1.4e-4 rel err.
// NCHAIN=1: single tf32 (rna-rounded operands)  -> ~2e-4 rel err.
// MODE 0: relu on n < relu_upto.  MODE 1: add bias[n].
// CTA tile 128x128x32, 256 threads, warp tile 32x64, double-buffered smem.
// ---------------------------------------------------------------------------
template <int NCHAIN, int MODE>
__global__ __launch_bounds__(256, 1) void mma_gemm(
    const float* __restrict__ A, const float* __restrict__ W,
    float* __restrict__ C, const float* __restrict__ bias,
    int M, int Nn, int K, int relu_upto)
{
    constexpr int SROW = 36;                 // 32 + 4 pad (conflict-free frags)
    constexpr int TILEF = 128 * SROW;        // floats per matrix tile
    constexpr int STAGEF = (1 + NCHAIN) * TILEF;
    extern __shared__ float sm[];

    const int tid = threadIdx.x;
    const int wid = tid >> 5;
    const int lane = tid & 31;
    const int g = lane >> 2;                 // groupID (0..7)
    const int tig = lane & 3;                // thread-in-group
    const int mwarp = (wid & 3) * 32;
    const int nwarp = (wid >> 2) * 64;
    const int m0 = blockIdx.y * 128;
    const int n0 = blockIdx.x * 128;

    const float* Ab = A + (size_t)m0 * K;
    const float* Wb = W + (size_t)n0 * K;

    float acc[2][8][4];
#pragma unroll
    for (int mt = 0; mt < 2; mt++)
#pragma unroll
        for (int nt = 0; nt < 8; nt++)
#pragma unroll
            for (int j = 0; j < 4; j++) acc[mt][nt][j] = 0.0f;

    float4 ra[4], rb[4];
    const int NK = K / 32;

    // prologue: load k-tile 0
#pragma unroll
    for (int i = 0; i < 4; i++) {
        int idx = tid + i * 256;
        int row = idx >> 3, c = (idx & 7) * 4;
        ra[i] = *(const float4*)(Ab + (size_t)row * K + c);
        rb[i] = *(const float4*)(Wb + (size_t)row * K + c);
    }

    for (int it = 0; it < NK; it++) {
        const int s = it & 1;
        float* sA  = sm + s * STAGEF;
        float* sBh = sA + TILEF;
        float* sBl = sBh + TILEF;            // only used when NCHAIN==2

        // store (round / split) this tile
#pragma unroll
        for (int i = 0; i < 4; i++) {
            int idx = tid + i * 256;
            int row = idx >> 3, c = (idx & 7) * 4;
            float4 ah;
            ah.x = tf32r(ra[i].x); ah.y = tf32r(ra[i].y);
            ah.z = tf32r(ra[i].z); ah.w = tf32r(ra[i].w);
            *(float4*)(sA + row * SROW + c) = ah;
            float4 bh;
            bh.x = tf32r(rb[i].x); bh.y = tf32r(rb[i].y);
            bh.z = tf32r(rb[i].z); bh.w = tf32r(rb[i].w);
            *(float4*)(sBh + row * SROW + c) = bh;
            if (NCHAIN == 2) {
                float4 bl;
                bl.x = tf32r(rb[i].x - bh.x); bl.y = tf32r(rb[i].y - bh.y);
                bl.z = tf32r(rb[i].z - bh.z); bl.w = tf32r(rb[i].w - bh.w);
                *(float4*)(sBl + row * SROW + c) = bl;
            }
        }
        __syncthreads();

        // prefetch next k-tile (overlaps mma loop)
        if (it + 1 < NK) {
            int kt = (it + 1) * 32;
#pragma unroll
            for (int i = 0; i < 4; i++) {
                int idx = tid + i * 256;
                int row = idx >> 3, c = (idx & 7) * 4;
                ra[i] = *(const float4*)(Ab + (size_t)row * K + kt + c);
                rb[i] = *(const float4*)(Wb + (size_t)row * K + kt + c);
            }
        }

        // mma over the 4 k-steps of this tile
#pragma unroll
        for (int kk = 0; kk < 4; kk++) {
            float afr[2][4];
#pragma unroll
            for (int mt = 0; mt < 2; mt++) {
                int base = (mwarp + mt * 16 + g) * SROW + kk * 8 + tig;
                afr[mt][0] = sA[base];
                afr[mt][1] = sA[base + 8 * SROW];
                afr[mt][2] = sA[base + 4];
                afr[mt][3] = sA[base + 8 * SROW + 4];
            }
#pragma unroll
            for (int ch = 0; ch < NCHAIN; ch++) {
                const float* sB = (ch == 0) ? sBh : sBl;
#pragma unroll
                for (int nt = 0; nt < 8; nt++) {
                    int baseb = (nwarp + nt * 8 + g) * SROW + kk * 8 + tig;
                    float b0 = sB[baseb];
                    float b1 = sB[baseb + 4];
#pragma unroll
                    for (int mt = 0; mt < 2; mt++)
                        mma_tf32(acc[mt][nt], afr[mt], b0, b1);
                }
            }
        }
        __syncthreads();
    }

    // epilogue
#pragma unroll
    for (int mt = 0; mt < 2; mt++) {
        int mA = m0 + mwarp + mt * 16 + g;
#pragma unroll
        for (int nt = 0; nt < 8; nt++) {
            int n = n0 + nwarp + nt * 8 + 2 * tig;
            float e0 = acc[mt][nt][0], e1 = acc[mt][nt][1];
            float e2 = acc[mt][nt][2], e3 = acc[mt][nt][3];
            if (MODE == 0) {
                if (n < relu_upto)     { e0 = fmaxf(e0, 0.f); e2 = fmaxf(e2, 0.f); }
                if (n + 1 < relu_upto) { e1 = fmaxf(e1, 0.f); e3 = fmaxf(e3, 0.f); }
            } else {
                float bb0 = bias[n], bb1 = bias[n + 1];
                e0 += bb0; e1 += bb1; e2 += bb0; e3 += bb1;
            }
            *(float2*)(C + (size_t)mA * Nn + n)       = make_float2(e0, e1);
            *(float2*)(C + (size_t)(mA + 8) * Nn + n) = make_float2(e2, e3);
        }
    }
}

// ---------------------------------------------------------------------------
// vk partial reduction (unchanged)
// ---------------------------------------------------------------------------
__global__ __launch_bounds__(256) void vk_partial_kernel(
    const float* __restrict__ qkv, float* __restrict__ part)
{
    const int blk = blockIdx.x;
    const int slice = blk & 7;
    const int head = blk >> 3;
    const int b = head >> 5;
    const int hh = head & 31;
    const int tid = threadIdx.x;

    __shared__ float ks[8][32];
    __shared__ float vs[8][32];

    float acc[5] = {0.f, 0.f, 0.f, 0.f, 0.f};

    const float* base = qkv + (size_t)b * Nx * NC3 + (size_t)(slice * 512) * NC3 + hh * 32;
    const int r = tid >> 5;
    const int e = tid & 31;

    for (int n0 = 0; n0 < 512; n0 += 8) {
        const float* p = base + (size_t)(n0 + r) * NC3 + e;
        float kreg = p[1024];
        float vreg = p[2048];
        __syncthreads();
        ks[r][e] = kreg;
        vs[r][e] = vreg;
        __syncthreads();
#pragma unroll
        for (int rr = 0; rr < 8; rr++) {
#pragma unroll
            for (int i = 0; i < 5; i++) {
                int idx = tid + 256 * i;
                if (idx < 1056) {
                    int d = idx >> 5;
                    int ee = idx & 31;
                    float vval = (d == 32) ? 1.0f : vs[rr][d];
                    acc[i] += vval * ks[rr][ee];
                }
            }
        }
    }
#pragma unroll
    for (int i = 0; i < 5; i++) {
        int idx = tid + 256 * i;
        if (idx < 1056) part[(size_t)blk * 1056 + idx] = acc[i];
    }
}

__global__ void vk_reduce_kernel(const float* __restrict__ part,
                                 float* __restrict__ vk)
{
    int idx = blockIdx.x * 256 + threadIdx.x;
    if (idx >= 128 * 1056) return;
    int head = idx / 1056;
    int j = idx % 1056;
    float s = 0.f;
#pragma unroll
    for (int sl = 0; sl < 8; sl++)
        s += part[(size_t)(head * 8 + sl) * 1056 + j];
    vk[idx] = s;
}

// ---------------------------------------------------------------------------
// att kernel (unchanged)
// ---------------------------------------------------------------------------
__global__ __launch_bounds__(128) void att_kernel(
    const float* __restrict__ qkv, const float* __restrict__ vk,
    float* __restrict__ att)
{
    const int blk = blockIdx.x;
    const int nch = blk & 31;
    const int head = blk >> 5;
    const int b = head >> 5;
    const int hh = head & 31;
    const int tid = threadIdx.x;

    __shared__ float vks[1056];
    __shared__ float qs[128][33];

    for (int i = tid; i < 1056; i += 128)
        vks[i] = vk[(size_t)head * 1056 + i];

    const float* qbase = qkv + (size_t)b * Nx * NC3 + (size_t)(nch * 128) * NC3 + hh * 32;
#pragma unroll
    for (int i = 0; i < 32; i++) {
        int idx = i * 128 + tid;
        int row = idx >> 5;
        int e = idx & 31;
        qs[row][e] = qbase[(size_t)row * NC3 + e];
    }
    __syncthreads();

    float qr[32];
#pragma unroll
    for (int e = 0; e < 32; e++) qr[e] = qs[tid][e];

    float den = 0.f;
#pragma unroll
    for (int e = 0; e < 32; e++) den += vks[1024 + e] * qr[e];
    float inv = 1.0f / (den + EPSV);

    float outv[32];
#pragma unroll
    for (int d = 0; d < 32; d++) {
        float s = 0.f;
#pragma unroll
        for (int e = 0; e < 32; e++) s += vks[d * 32 + e] * qr[e];
        outv[d] = s * inv;
    }
    __syncthreads();
#pragma unroll
    for (int d = 0; d < 32; d++) qs[tid][d] = outv[d];
    __syncthreads();

    float* obase = att + (size_t)b * Nx * Cx + (size_t)(nch * 128) * Cx + hh * 32;
#pragma unroll
    for (int i = 0; i < 32; i++) {
        int idx = i * 128 + tid;
        int row = idx >> 5;
        int d = idx & 31;
        obase[(size_t)row * Cx + d] = qs[row][d];
    }
}

// ---------------------------------------------------------------------------
extern "C" void kernel_launch(void* const* d_in, const int* in_sizes, int n_in,
                              void* d_out, int out_size)
{
    const float* x     = (const float*)d_in[0];
    const float* Wqkv  = (const float*)d_in[1];
    const float* Wproj = (const float*)d_in[2];
    const float* bproj = (const float*)d_in[3];
    float* out = (float*)d_out;

    float *qkv, *part, *vk, *att;
    cudaGetSymbolAddress((void**)&qkv,  g_qkv);
    cudaGetSymbolAddress((void**)&part, g_vkpart);
    cudaGetSymbolAddress((void**)&vk,   g_vk);
    cudaGetSymbolAddress((void**)&att,  g_att);

    const int M = Bx * Nx;   // 16384

    const int smem1 = 2 * 3 * 128 * 36 * 4;   // NCHAIN=2: 110592 B
    const int smem2 = 2 * 2 * 128 * 36 * 4;   // NCHAIN=1:  73728 B
    cudaFuncSetAttribute(mma_gemm<2, 0>,
                         cudaFuncAttributeMaxDynamicSharedMemorySize, smem1);
    cudaFuncSetAttribute(mma_gemm<1, 1>,
                         cudaFuncAttributeMaxDynamicSharedMemorySize, smem2);

    // 1) qkv = x @ Wqkv^T (2-chain tf32; W split exactly), relu on n < 2048
    mma_gemm<2, 0><<<dim3(NC3 / 128, M / 128), 256, smem1>>>(
        x, Wqkv, qkv, nullptr, M, NC3, Cx, 2 * Cx);

    // 2) vk partials + reduce
    vk_partial_kernel<<<1024, 256>>>(qkv, part);
    vk_reduce_kernel<<<(128 * 1056 + 255) / 256, 256>>>(part, vk);

    // 3) attention normalize -> att (B,N,C)
    att_kernel<<<4096, 128>>>(qkv, vk, att);

    // 4) out = att @ Wproj^T + b  (single tf32, rna-rounded)
    mma_gemm<1, 1><<<dim3(Cx / 128, M / 128), 256, smem2>>>(
        att, Wproj, out, bproj, M, Cx, Cx, 0);
}

// round 4
// speedup vs baseline: 2.1429x; 1.0474x over previous
#include <cuda_runtime.h>
#include <cstdint>

#define Bx 4
#define Nx 4096
#define Cx 1024
#define NC3 3072
#define EPSV 1e-15f

// Scratch (device globals — no allocation allowed)
__device__ float g_qkv[(size_t)Bx * Nx * NC3];        // 192 MB
__device__ float g_vkpart[1024 * 1056];               // 4.3 MB
__device__ float g_vk[128 * 1056];                    // 0.5 MB
__device__ float g_att[(size_t)Bx * Nx * Cx];         // 64 MB

__device__ __forceinline__ float tf32r(float a) {
    uint32_t b;
    asm("cvt.rna.tf32.f32 %0, %1;" : "=r"(b) : "f"(a));
    return __uint_as_float(b);
}
__device__ __forceinline__ uint32_t smem_u32(const void* p) {
    uint32_t a;
    asm("{ .reg .u64 t; cvta.to.shared.u64 t, %1; cvt.u32.u64 %0, t; }"
        : "=r"(a) : "l"(p));
    return a;
}
__device__ __forceinline__ void cpa16(uint32_t s, const float* g) {
    asm volatile("cp.async.cg.shared.global [%0], [%1], 16;"
                 :: "r"(s), "l"(g) : "memory");
}
__device__ __forceinline__ void mma_tf32(float d[4], const float a[4],
                                         float b0, float b1) {
    asm("mma.sync.aligned.m16n8k8.row.col.f32.tf32.tf32.f32 "
        "{%0,%1,%2,%3}, {%4,%5,%6,%7}, {%8,%9}, {%0,%1,%2,%3};"
        : "+f"(d[0]), "+f"(d[1]), "+f"(d[2]), "+f"(d[3])
        : "r"(__float_as_uint(a[0])), "r"(__float_as_uint(a[1])),
          "r"(__float_as_uint(a[2])), "r"(__float_as_uint(a[3])),
          "r"(__float_as_uint(b0)), "r"(__float_as_uint(b1)));
}

// ---------------------------------------------------------------------------
// Tensor-core GEMM (legacy mma.sync tf32): C[m,n] = sum_k A[m,k]*W[n,k]
// Raw fp32 staged to smem via cp.async; rna-rounding / hi-lo split done at
// fragment-load time. NCHAIN=2: W split hi+lo (chained). NCHAIN=1: single.
// CTA tile 256x128x32, 8 warps, warp tile 64x64, 2-stage cp.async pipeline.
// MODE 0: relu on n < relu_upto.  MODE 1: add bias[n].
// ---------------------------------------------------------------------------
template <int NCHAIN, int MODE>
__global__ __launch_bounds__(256, 1) void mma_gemm(
    const float* __restrict__ A, const float* __restrict__ W,
    float* __restrict__ C, const float* __restrict__ bias,
    int M, int Nn, int K, int relu_upto)
{
    constexpr int SROW = 36;                    // 32 + 4 pad floats
    constexpr int AROWS = 256, BROWS = 128;
    constexpr int STAGEF = (AROWS + BROWS) * SROW;
    extern __shared__ float sm[];
    const uint32_t sb = smem_u32(sm);

    const int tid = threadIdx.x;
    const int wid = tid >> 5;
    const int lane = tid & 31;
    const int g = lane >> 2;
    const int tig = lane & 3;
    const int warp_m = (wid & 3) * 64;
    const int warp_n = (wid >> 2) * 64;
    const int m0 = blockIdx.y * 256;
    const int n0 = blockIdx.x * 128;

    const float* Ab = A + (size_t)m0 * K;
    const float* Wb = W + (size_t)n0 * K;

    float acc[4][8][4];
#pragma unroll
    for (int mt = 0; mt < 4; mt++)
#pragma unroll
        for (int nt = 0; nt < 8; nt++)
#pragma unroll
            for (int j = 0; j < 4; j++) acc[mt][nt][j] = 0.0f;

    const int NK = K / 32;
    const int arow = tid >> 3;                  // 0..31 within 256-thread pass
    const int acol = (tid & 7) * 4;

    // issue cp.async loads of k-tile `it` into stage `s`
    auto issue = [&](int it, int s) {
        const int kt = it * 32;
        const uint32_t as = sb + (uint32_t)s * STAGEF * 4;
        const uint32_t bs = as + AROWS * SROW * 4;
#pragma unroll
        for (int i = 0; i < 8; i++) {
            int row = arow + i * 32;
            cpa16(as + (uint32_t)(row * SROW + acol) * 4,
                  Ab + (size_t)row * K + kt + acol);
        }
#pragma unroll
        for (int i = 0; i < 4; i++) {
            int row = arow + i * 32;
            cpa16(bs + (uint32_t)(row * SROW + acol) * 4,
                  Wb + (size_t)row * K + kt + acol);
        }
        asm volatile("cp.async.commit_group;" ::: "memory");
    };

    issue(0, 0);

    for (int it = 0; it < NK; it++) {
        if (it + 1 < NK) {
            issue(it + 1, (it + 1) & 1);
            asm volatile("cp.async.wait_group 1;" ::: "memory");
        } else {
            asm volatile("cp.async.wait_group 0;" ::: "memory");
        }
        __syncthreads();

        const float* sA = sm + (it & 1) * STAGEF;
        const float* sB = sA + AROWS * SROW;

#pragma unroll
        for (int kk = 0; kk < 4; kk++) {
            float ah[4][4];
#pragma unroll
            for (int mt = 0; mt < 4; mt++) {
                int base = (warp_m + mt * 16 + g) * SROW + kk * 8 + tig;
                ah[mt][0] = tf32r(sA[base]);
                ah[mt][1] = tf32r(sA[base + 8 * SROW]);
                ah[mt][2] = tf32r(sA[base + 4]);
                ah[mt][3] = tf32r(sA[base + 8 * SROW + 4]);
            }
#pragma unroll
            for (int nt = 0; nt < 8; nt++) {
                int bb = (warp_n + nt * 8 + g) * SROW + kk * 8 + tig;
                float b0 = sB[bb];
                float b1 = sB[bb + 4];
                float b0h = tf32r(b0), b1h = tf32r(b1);
#pragma unroll
                for (int mt = 0; mt < 4; mt++)
                    mma_tf32(acc[mt][nt], ah[mt], b0h, b1h);
                if (NCHAIN == 2) {
                    float b0l = tf32r(b0 - b0h), b1l = tf32r(b1 - b1h);
#pragma unroll
                    for (int mt = 0; mt < 4; mt++)
                        mma_tf32(acc[mt][nt], ah[mt], b0l, b1l);
                }
            }
        }
        __syncthreads();   // done reading this stage before next issue overwrites
    }

    // epilogue
#pragma unroll
    for (int mt = 0; mt < 4; mt++) {
        int mA = m0 + warp_m + mt * 16 + g;
#pragma unroll
        for (int nt = 0; nt < 8; nt++) {
            int n = n0 + warp_n + nt * 8 + 2 * tig;
            float e0 = acc[mt][nt][0], e1 = acc[mt][nt][1];
            float e2 = acc[mt][nt][2], e3 = acc[mt][nt][3];
            if (MODE == 0) {
                if (n < relu_upto)     { e0 = fmaxf(e0, 0.f); e2 = fmaxf(e2, 0.f); }
                if (n + 1 < relu_upto) { e1 = fmaxf(e1, 0.f); e3 = fmaxf(e3, 0.f); }
            } else {
                float bb0 = bias[n], bb1 = bias[n + 1];
                e0 += bb0; e1 += bb1; e2 += bb0; e3 += bb1;
            }
            *(float2*)(C + (size_t)mA * Nn + n)       = make_float2(e0, e1);
            *(float2*)(C + (size_t)(mA + 8) * Nn + n) = make_float2(e2, e3);
        }
    }
}

// ---------------------------------------------------------------------------
// vk partial reduction (unchanged)
// ---------------------------------------------------------------------------
__global__ __launch_bounds__(256) void vk_partial_kernel(
    const float* __restrict__ qkv, float* __restrict__ part)
{
    const int blk = blockIdx.x;
    const int slice = blk & 7;
    const int head = blk >> 3;
    const int b = head >> 5;
    const int hh = head & 31;
    const int tid = threadIdx.x;

    __shared__ float ks[8][32];
    __shared__ float vs[8][32];

    float acc[5] = {0.f, 0.f, 0.f, 0.f, 0.f};

    const float* base = qkv + (size_t)b * Nx * NC3 + (size_t)(slice * 512) * NC3 + hh * 32;
    const int r = tid >> 5;
    const int e = tid & 31;

    for (int n0 = 0; n0 < 512; n0 += 8) {
        const float* p = base + (size_t)(n0 + r) * NC3 + e;
        float kreg = p[1024];
        float vreg = p[2048];
        __syncthreads();
        ks[r][e] = kreg;
        vs[r][e] = vreg;
        __syncthreads();
#pragma unroll
        for (int rr = 0; rr < 8; rr++) {
#pragma unroll
            for (int i = 0; i < 5; i++) {
                int idx = tid + 256 * i;
                if (idx < 1056) {
                    int d = idx >> 5;
                    int ee = idx & 31;
                    float vval = (d == 32) ? 1.0f : vs[rr][d];
                    acc[i] += vval * ks[rr][ee];
                }
            }
        }
    }
#pragma unroll
    for (int i = 0; i < 5; i++) {
        int idx = tid + 256 * i;
        if (idx < 1056) part[(size_t)blk * 1056 + idx] = acc[i];
    }
}

__global__ void vk_reduce_kernel(const float* __restrict__ part,
                                 float* __restrict__ vk)
{
    int idx = blockIdx.x * 256 + threadIdx.x;
    if (idx >= 128 * 1056) return;
    int head = idx / 1056;
    int j = idx % 1056;
    float s = 0.f;
#pragma unroll
    for (int sl = 0; sl < 8; sl++)
        s += part[(size_t)(head * 8 + sl) * 1056 + j];
    vk[idx] = s;
}

// ---------------------------------------------------------------------------
// att kernel (unchanged)
// ---------------------------------------------------------------------------
__global__ __launch_bounds__(128) void att_kernel(
    const float* __restrict__ qkv, const float* __restrict__ vk,
    float* __restrict__ att)
{
    const int blk = blockIdx.x;
    const int nch = blk & 31;
    const int head = blk >> 5;
    const int b = head >> 5;
    const int hh = head & 31;
    const int tid = threadIdx.x;

    __shared__ float vks[1056];
    __shared__ float qs[128][33];

    for (int i = tid; i < 1056; i += 128)
        vks[i] = vk[(size_t)head * 1056 + i];

    const float* qbase = qkv + (size_t)b * Nx * NC3 + (size_t)(nch * 128) * NC3 + hh * 32;
#pragma unroll
    for (int i = 0; i < 32; i++) {
        int idx = i * 128 + tid;
        int row = idx >> 5;
        int e = idx & 31;
        qs[row][e] = qbase[(size_t)row * NC3 + e];
    }
    __syncthreads();

    float qr[32];
#pragma unroll
    for (int e = 0; e < 32; e++) qr[e] = qs[tid][e];

    float den = 0.f;
#pragma unroll
    for (int e = 0; e < 32; e++) den += vks[1024 + e] * qr[e];
    float inv = 1.0f / (den + EPSV);

    float outv[32];
#pragma unroll
    for (int d = 0; d < 32; d++) {
        float s = 0.f;
#pragma unroll
        for (int e = 0; e < 32; e++) s += vks[d * 32 + e] * qr[e];
        outv[d] = s * inv;
    }
    __syncthreads();
#pragma unroll
    for (int d = 0; d < 32; d++) qs[tid][d] = outv[d];
    __syncthreads();

    float* obase = att + (size_t)b * Nx * Cx + (size_t)(nch * 128) * Cx + hh * 32;
#pragma unroll
    for (int i = 0; i < 32; i++) {
        int idx = i * 128 + tid;
        int row = idx >> 5;
        int d = idx & 31;
        obase[(size_t)row * Cx + d] = qs[row][d];
    }
}

// ---------------------------------------------------------------------------
extern "C" void kernel_launch(void* const* d_in, const int* in_sizes, int n_in,
                              void* d_out, int out_size)
{
    const float* x     = (const float*)d_in[0];
    const float* Wqkv  = (const float*)d_in[1];
    const float* Wproj = (const float*)d_in[2];
    const float* bproj = (const float*)d_in[3];
    float* out = (float*)d_out;

    float *qkv, *part, *vk, *att;
    cudaGetSymbolAddress((void**)&qkv,  g_qkv);
    cudaGetSymbolAddress((void**)&part, g_vkpart);
    cudaGetSymbolAddress((void**)&vk,   g_vk);
    cudaGetSymbolAddress((void**)&att,  g_att);

    const int M = Bx * Nx;   // 16384

    const int smem = 2 * (256 + 128) * 36 * 4;   // 110592 B
    cudaFuncSetAttribute(mma_gemm<2, 0>,
                         cudaFuncAttributeMaxDynamicSharedMemorySize, smem);
    cudaFuncSetAttribute(mma_gemm<1, 1>,
                         cudaFuncAttributeMaxDynamicSharedMemorySize, smem);

    // 1) qkv = x @ Wqkv^T (2-chain tf32; W split), relu on n < 2048
    mma_gemm<2, 0><<<dim3(NC3 / 128, M / 256), 256, smem>>>(
        x, Wqkv, qkv, nullptr, M, NC3, Cx, 2 * Cx);

    // 2) vk partials + reduce
    vk_partial_kernel<<<1024, 256>>>(qkv, part);
    vk_reduce_kernel<<<(128 * 1056 + 255) / 256, 256>>>(part, vk);

    // 3) attention normalize -> att (B,N,C)
    att_kernel<<<4096, 128>>>(qkv, vk, att);

    // 4) out = att @ Wproj^T + b  (single tf32, rna-rounded)
    mma_gemm<1, 1><<<dim3(Cx / 128, M / 128 / 2), 256, smem>>>(
        att, Wproj, out, bproj, M, Cx, Cx, 0);
}